// round 3
// baseline (speedup 1.0000x reference)
#include <cuda_runtime.h>
#include <cstdint>

#define BB 32
#define HH 300
#define WW 300

typedef unsigned long long u64;

// ---------------- device scratch (no allocs allowed) ----------------
__device__ float g_buf[69120000];          // [32][24][300][300]
__device__ float p5_buf[BB*8*60*60];
__device__ float p10_buf[BB*8*30*30];
__device__ float p15_buf[BB*8*20*20];
__device__ float part_buf[3200*16];
__device__ float bn_buf[16];

// ---------------- f32x2 helpers ----------------
__device__ __forceinline__ u64 pk2(float lo, float hi) {
    u64 r; asm("mov.b64 %0,{%1,%2};" : "=l"(r) : "f"(lo), "f"(hi)); return r;
}
__device__ __forceinline__ u64 bc2(float2 v) {
    u64 r; asm("mov.b64 %0,{%1,%2};" : "=l"(r) : "f"(v.x), "f"(v.y)); return r;
}
__device__ __forceinline__ void fma2(u64& d, u64 a, u64 b) {
    asm("fma.rn.f32x2 %0,%1,%2,%0;" : "+l"(d) : "l"(a), "l"(b));
}
__device__ __forceinline__ float2 up2(u64 v) {
    float2 f; asm("mov.b64 {%0,%1},%2;" : "=f"(f.x), "=f"(f.y) : "l"(v)); return f;
}

// ---------------- K1a: 5x5 average pool ----------------
__global__ void k_pool5(const float* __restrict__ x) {
    int i = blockIdx.x * blockDim.x + threadIdx.x;
    if (i >= BB*8*60*60) return;
    int px = i % 60; int t = i / 60;
    int py = t % 60; t /= 60;
    int c  = t % 8;  int b = t / 8;
    const float* base = x + ((size_t)(b*8 + c)*HH + py*5)*WW + px*5;
    float s = 0.f;
    #pragma unroll
    for (int r = 0; r < 5; r++)
        #pragma unroll
        for (int q = 0; q < 5; q++) s += base[r*WW + q];
    p5_buf[i] = s * (1.0f/25.0f);
}

// ---------------- K1b: pool10/pool15 from pool5 (exact) ----------------
__global__ void k_poolrest() {
    int i = blockIdx.x * blockDim.x + threadIdx.x;
    if (i < BB*8*30*30) {
        int px = i % 30; int t = i / 30;
        int py = t % 30; t /= 30;
        int c  = t % 8;  int b = t / 8;
        const float* base = p5_buf + ((b*8 + c)*60 + py*2)*60 + px*2;
        p10_buf[i] = (base[0] + base[1] + base[60] + base[61]) * 0.25f;
    }
    int j = i - BB*8*30*30;
    if (j >= 0 && j < BB*8*20*20) {
        int px = j % 20; int t = j / 20;
        int py = t % 20; t /= 20;
        int c  = t % 8;  int b = t / 8;
        const float* base = p5_buf + ((b*8 + c)*60 + py*3)*60 + px*3;
        float s = 0.f;
        #pragma unroll
        for (int r = 0; r < 3; r++)
            #pragma unroll
            for (int q = 0; q < 3; q++) s += base[r*60 + q];
        p15_buf[j] = s * (1.0f/9.0f);
    }
}

// ---------------- K2a: three concat-convs -> g_in (f32x2) ----------------
// tile 30x30 out (32x32 input halo). 225 threads do a 2x2 quad each.
// smem floats: xs 8192 | us 8192 | wq 2304 (576 quads of (wa,wa,wb,wb)) | bs 8
__global__ void __launch_bounds__(256, 2)
k_conv1(const float* __restrict__ x,
        const float* __restrict__ w5,  const float* __restrict__ b5,
        const float* __restrict__ w10, const float* __restrict__ b10,
        const float* __restrict__ w15, const float* __restrict__ b15) {
    extern __shared__ float sm[];
    float* xs = sm;               // 8192
    float* us = sm + 8192;        // 8192
    float* wq = sm + 16384;       // 2304 (16B aligned: 64KB offset)
    float* bs = sm + 18688;       // 8
    const ulonglong2* wq2 = reinterpret_cast<const ulonglong2*>(wq);
    int tid = threadIdx.x;
    int b  = blockIdx.z;
    int oy = blockIdx.y * 30, ox = blockIdx.x * 30;

    // x tile (zero padded), 8 ch
    for (int i = tid; i < 8192; i += 256) {
        int col = i & 31, r = (i >> 5) & 31, c = i >> 10;
        int gy = oy - 1 + r, gx = ox - 1 + col;
        float v = 0.f;
        if (gy >= 0 && gy < HH && gx >= 0 && gx < WW)
            v = x[((size_t)(b*8 + c)*HH + gy)*WW + gx];
        xs[i] = v;
    }

    int qr = tid / 15, qc = tid % 15;
    int r0 = 2*qr, c0 = 2*qc;     // local output coords (valid if tid<225)

    for (int phase = 0; phase < 3; phase++) {
        const float *wk, *bk, *pk;
        int k, PH, PW, cg;
        if (phase == 0)      { wk = w5;  bk = b5;  pk = p5_buf;  k = 5;  PH = 60; PW = 60; cg = 0;  }
        else if (phase == 1) { wk = w10; bk = b10; pk = p10_buf; k = 10; PH = 30; PW = 30; cg = 8;  }
        else                 { wk = w15; bk = b15; pk = p15_buf; k = 15; PH = 20; PW = 20; cg = 16; }

        __syncthreads();  // prior phase compute done before overwriting us/wq
        for (int i = tid; i < 8192; i += 256) {
            int col = i & 31, r = (i >> 5) & 31, c = i >> 10;
            int gy = oy - 1 + r, gx = ox - 1 + col;
            float v = 0.f;
            if (gy >= 0 && gy < HH && gx >= 0 && gx < WW)
                v = pk[((b*8 + c)*PH + gy / k)*PW + gx / k];
            us[i] = v;
        }
        // weight quads: (o, icp, tap) -> (w[o][2icp][tap] dup, w[o][2icp+1][tap] dup)
        for (int e = tid; e < 576; e += 256) {
            int tap = e % 9; int t = e / 9;
            int icp = t % 8; int o = t / 8;
            float wa = wk[(o*16 + 2*icp    )*9 + tap];
            float wb = wk[(o*16 + 2*icp + 1)*9 + tap];
            reinterpret_cast<float4*>(wq)[e] = make_float4(wa, wa, wb, wb);
        }
        if (tid < 8) bs[tid] = bk[tid];
        __syncthreads();

        if (tid < 225) {
            u64 acc[8][2];
            #pragma unroll
            for (int o = 0; o < 8; o++) {
                u64 bi = pk2(bs[o], bs[o]);
                acc[o][0] = bi; acc[o][1] = bi;
            }
            #pragma unroll 1
            for (int icp = 0; icp < 8; icp++) {
                const float* srca = (icp < 4) ? (xs + (2*icp)*1024)
                                              : (us + (2*(icp-4))*1024);
                u64 Pa[4][3], Pb[4][3];
                #pragma unroll
                for (int rr = 0; rr < 4; rr++) {
                    const float* rp = srca + (r0 + rr)*32 + c0;
                    float2 a = *reinterpret_cast<const float2*>(rp);
                    float2 c = *reinterpret_cast<const float2*>(rp + 2);
                    Pa[rr][0] = bc2(a); Pa[rr][1] = pk2(a.y, c.x); Pa[rr][2] = bc2(c);
                    const float* rq = rp + 1024;
                    float2 d = *reinterpret_cast<const float2*>(rq);
                    float2 e = *reinterpret_cast<const float2*>(rq + 2);
                    Pb[rr][0] = bc2(d); Pb[rr][1] = pk2(d.y, e.x); Pb[rr][2] = bc2(e);
                }
                #pragma unroll
                for (int o = 0; o < 8; o++) {
                    const ulonglong2* wr = wq2 + (o*8 + icp)*9;
                    #pragma unroll
                    for (int tap = 0; tap < 9; tap++) {
                        ulonglong2 w = wr[tap];
                        int r = tap / 3, q = tap % 3;
                        fma2(acc[o][0], w.x, Pa[r][q]);
                        fma2(acc[o][1], w.x, Pa[r+1][q]);
                        fma2(acc[o][0], w.y, Pb[r][q]);
                        fma2(acc[o][1], w.y, Pb[r+1][q]);
                    }
                }
            }
            #pragma unroll
            for (int o = 0; o < 8; o++)
                #pragma unroll
                for (int rr = 0; rr < 2; rr++) {
                    float2 v = up2(acc[o][rr]);
                    *reinterpret_cast<float2*>(
                        &g_buf[(((size_t)b*24 + cg + o)*HH + oy + r0 + rr)*WW + ox + c0]) = v;
                }
        }
    }
}

// ---------------- K2b: gated conv pair + BN partials (f32x2) ----------------
// two smem passes of 12 channels; accumulators persist in regs.
// smem floats: gs 12288 | wq 6912 (1728 quads (g,g,m,m)) | bias 16
__global__ void __launch_bounds__(256, 2)
k_conv2(const float* __restrict__ gw, const float* __restrict__ gb,
        const float* __restrict__ mw, const float* __restrict__ mb,
        float* __restrict__ out) {
    extern __shared__ float sm[];
    float* gs = sm;               // 12288
    float* wq = sm + 12288;       // 6912 (16B aligned: 48KB offset)
    float* bsg = sm + 19200;      // 8
    float* bsm = sm + 19208;      // 8
    const ulonglong2* wq2 = reinterpret_cast<const ulonglong2*>(wq);
    int tid = threadIdx.x;
    int b  = blockIdx.z;
    int oy = blockIdx.y * 30, ox = blockIdx.x * 30;

    // weight quads (all 24 ic): (o, ic, tap) -> (gw dup, mw dup)
    for (int e = tid; e < 1728; e += 256) {
        float g = gw[e];
        float m = mw[e];
        reinterpret_cast<float4*>(wq)[e] = make_float4(g, g, m, m);
    }
    if (tid < 8) { bsg[tid] = gb[tid]; bsm[tid] = mb[tid]; }

    int qr = tid / 15, qc = tid % 15;
    int r0 = 2*qr, c0 = 2*qc;

    u64 aG[8][2], aM[8][2];
    #pragma unroll
    for (int o = 0; o < 8; o++) { aG[o][0]=0; aG[o][1]=0; aM[o][0]=0; aM[o][1]=0; }

    for (int pass = 0; pass < 2; pass++) {
        __syncthreads();
        for (int i = tid; i < 12288; i += 256) {
            int col = i & 31, r = (i >> 5) & 31, c = (i >> 10) + pass*12;
            int gy = oy - 1 + r, gx = ox - 1 + col;
            float v = 0.f;
            if (gy >= 0 && gy < HH && gx >= 0 && gx < WW)
                v = g_buf[(((size_t)b*24 + c)*HH + gy)*WW + gx];
            gs[i] = v;
        }
        __syncthreads();

        if (tid < 225) {
            if (pass == 0) {
                #pragma unroll
                for (int o = 0; o < 8; o++) {
                    aG[o][0] = pk2(bsg[o], bsg[o]); aG[o][1] = aG[o][0];
                    aM[o][0] = pk2(bsm[o], bsm[o]); aM[o][1] = aM[o][0];
                }
            }
            #pragma unroll 1
            for (int icl = 0; icl < 12; icl++) {
                const float* src = gs + icl*1024;
                u64 P[4][3];
                #pragma unroll
                for (int rr = 0; rr < 4; rr++) {
                    const float* rp = src + (r0 + rr)*32 + c0;
                    float2 a = *reinterpret_cast<const float2*>(rp);
                    float2 c = *reinterpret_cast<const float2*>(rp + 2);
                    P[rr][0] = bc2(a); P[rr][1] = pk2(a.y, c.x); P[rr][2] = bc2(c);
                }
                #pragma unroll
                for (int o = 0; o < 8; o++) {
                    const ulonglong2* wr = wq2 + (o*24 + pass*12 + icl)*9;
                    #pragma unroll
                    for (int tap = 0; tap < 9; tap++) {
                        ulonglong2 w = wr[tap];
                        int r = tap / 3, q = tap % 3;
                        fma2(aG[o][0], w.x, P[r][q]);
                        fma2(aG[o][1], w.x, P[r+1][q]);
                        fma2(aM[o][0], w.y, P[r][q]);
                        fma2(aM[o][1], w.y, P[r+1][q]);
                    }
                }
            }
        }
    }

    // epilogue: gate, store, stats
    float lsum[8], lss[8];
    #pragma unroll
    for (int o = 0; o < 8; o++) { lsum[o] = 0.f; lss[o] = 0.f; }

    if (tid < 225) {
        #pragma unroll
        for (int o = 0; o < 8; o++)
            #pragma unroll
            for (int rr = 0; rr < 2; rr++) {
                float2 g = up2(aG[o][rr]);
                float2 m = up2(aM[o][rr]);
                float y0 = g.x / (1.f + __expf(-m.x));
                float y1 = g.y / (1.f + __expf(-m.y));
                float2 st; st.x = y0; st.y = y1;
                *reinterpret_cast<float2*>(
                    &out[(((size_t)b*8 + o)*HH + oy + r0 + rr)*WW + ox + c0]) = st;
                lsum[o] += y0 + y1;
                lss[o]  += y0*y0 + y1*y1;
            }
    }

    #pragma unroll
    for (int o = 0; o < 8; o++)
        for (int d = 16; d > 0; d >>= 1) {
            lsum[o] += __shfl_xor_sync(0xffffffffu, lsum[o], d);
            lss[o]  += __shfl_xor_sync(0xffffffffu, lss[o],  d);
        }
    __syncthreads();  // gs reuse for cross-warp reduction
    int wid = tid >> 5, lane = tid & 31;
    if (lane == 0) {
        #pragma unroll
        for (int o = 0; o < 8; o++) {
            gs[wid*16 + o]     = lsum[o];
            gs[wid*16 + 8 + o] = lss[o];
        }
    }
    __syncthreads();
    if (tid < 16) {
        float s = 0.f;
        #pragma unroll
        for (int w2 = 0; w2 < 8; w2++) s += gs[w2*16 + tid];
        int blin = (blockIdx.z * 10 + blockIdx.y) * 10 + blockIdx.x;
        part_buf[blin*16 + tid] = s;
    }
}

// ---------------- K3: final BN stats ----------------
__global__ void k_stats(const float* __restrict__ gamma, const float* __restrict__ beta) {
    __shared__ double red[16*9];
    int tid = threadIdx.x;
    int wid = tid >> 5, lane = tid & 31;
    double acc[16];
    #pragma unroll
    for (int v = 0; v < 16; v++) acc[v] = 0.0;
    for (int i = tid; i < 3200; i += 256) {
        #pragma unroll
        for (int v = 0; v < 16; v++) acc[v] += (double)part_buf[i*16 + v];
    }
    #pragma unroll
    for (int v = 0; v < 16; v++)
        for (int d = 16; d > 0; d >>= 1)
            acc[v] += __shfl_xor_sync(0xffffffffu, acc[v], d);
    if (lane == 0) {
        #pragma unroll
        for (int v = 0; v < 16; v++) red[wid*16 + v] = acc[v];
    }
    __syncthreads();
    if (tid < 16) {
        double s = 0.0;
        #pragma unroll
        for (int w = 0; w < 8; w++) s += red[w*16 + tid];
        red[128 + tid] = s;
    }
    __syncthreads();
    if (tid < 8) {
        const double N = 2880000.0;
        double mean = red[128 + tid] / N;
        double ex2  = red[136 + tid] / N;
        double var  = ex2 - mean * mean;
        double scale = (double)gamma[tid] / sqrt(var + 1e-5);
        double shift = (double)beta[tid] - mean * scale;
        bn_buf[tid]     = (float)scale;
        bn_buf[8 + tid] = (float)shift;
    }
}

// ---------------- K4: in-place normalize ----------------
__global__ void k_norm(float* __restrict__ out) {
    int i = blockIdx.x * blockDim.x + threadIdx.x;
    if (i >= 5760000) return;
    int c = (i / 22500) & 7;
    float sc = bn_buf[c], sh = bn_buf[8 + c];
    float4 v = reinterpret_cast<float4*>(out)[i];
    v.x = v.x * sc + sh;
    v.y = v.y * sc + sh;
    v.z = v.z * sc + sh;
    v.w = v.w * sc + sh;
    reinterpret_cast<float4*>(out)[i] = v;
}

// ---------------- launch ----------------
extern "C" void kernel_launch(void* const* d_in, const int* in_sizes, int n_in,
                              void* d_out, int out_size) {
    const float* x    = (const float*)d_in[0];
    const float* w5   = (const float*)d_in[1];
    const float* b5   = (const float*)d_in[2];
    const float* w10  = (const float*)d_in[3];
    const float* b10  = (const float*)d_in[4];
    const float* w15  = (const float*)d_in[5];
    const float* b15  = (const float*)d_in[6];
    const float* gw   = (const float*)d_in[7];
    const float* gb   = (const float*)d_in[8];
    const float* mw   = (const float*)d_in[9];
    const float* mb   = (const float*)d_in[10];
    const float* gamma= (const float*)d_in[11];
    const float* beta = (const float*)d_in[12];
    float* out = (float*)d_out;

    cudaFuncSetAttribute(k_conv1, cudaFuncAttributeMaxDynamicSharedMemorySize, 18696*4);
    cudaFuncSetAttribute(k_conv2, cudaFuncAttributeMaxDynamicSharedMemorySize, 19216*4);

    k_pool5   <<<(921600 + 255) / 256, 256>>>(x);
    k_poolrest<<<(332800 + 255) / 256, 256>>>();

    dim3 grid(10, 10, 32);
    k_conv1<<<grid, 256, 18696*4>>>(x, w5, b5, w10, b10, w15, b15);
    k_conv2<<<grid, 256, 19216*4>>>(gw, gb, mw, mb, out);

    k_stats<<<1, 256>>>(gamma, beta);
    k_norm <<<(5760000 + 255) / 256, 256>>>(out);
}

// round 7
// speedup vs baseline: 1.1545x; 1.1545x over previous
#include <cuda_runtime.h>
#include <cuda_bf16.h>
#include <cstdint>

typedef unsigned int u32;

#define HH 300
#define WW 300

// output tile geometry
#define TW 32          // out cols per block
#define TH 16          // out rows per block
#define INW 34         // in-tile width  (TW + 2 halo)
#define INH 18         // in-tile height (TH + 2 halo)
#define PLANE (INH*INW)   // 612
#define GX 10
#define GY 19
#define NBLK (GX*GY*32)   // 6080

// conv1: A-channels = [x(8), up5(8), up10(8), up15(8)] -> K = 32*9 = 288
#define K1 288
#define STEPS1 18
#define NT1 3          // N = 24
// conv2: 24 ch -> K = 216, padded 224
#define K2 224
#define K2R 216
#define STEPS2 14
#define NT2 2          // N = 16 (gate 8 + mask 8)

// ---------------- device scratch ----------------
__device__ u32   g_pk[32u*24u*HH*WW];        // packed (hi<<16|lo) bf16 pairs
__device__ float p5f[32*8*60*60];
__device__ float p10f[32*8*30*30];
__device__ float p15f[32*8*20*20];
__device__ u32   bfrag1[STEPS1*NT1*2*32*2];  // 6912
__device__ u32   bfrag2[STEPS2*NT2*2*32*2];  // 3584
__device__ float part_buf[NBLK*16];
__device__ float bn_buf[16];

// ---------------- helpers ----------------
__device__ __forceinline__ u32 pack_split(float v) {
    __nv_bfloat16 h = __float2bfloat16(v);
    float hf = __bfloat162float(h);
    __nv_bfloat16 l = __float2bfloat16(v - hf);
    return ((u32)__bfloat16_as_ushort(h) << 16) | (u32)__bfloat16_as_ushort(l);
}
__device__ __forceinline__ void mma_bf16(float* d, u32 a0, u32 a1, u32 a2, u32 a3,
                                         u32 b0, u32 b1) {
    asm volatile(
        "mma.sync.aligned.m16n8k16.row.col.f32.bf16.bf16.f32 "
        "{%0,%1,%2,%3},{%4,%5,%6,%7},{%8,%9},{%0,%1,%2,%3};"
        : "+f"(d[0]), "+f"(d[1]), "+f"(d[2]), "+f"(d[3])
        : "r"(a0), "r"(a1), "r"(a2), "r"(a3), "r"(b0), "r"(b1));
}

// ---------------- pools (fp32) ----------------
__global__ void k_pool5(const float* __restrict__ x) {
    int i = blockIdx.x * blockDim.x + threadIdx.x;
    if (i >= 32*8*60*60) return;
    int px = i % 60; int t = i / 60;
    int py = t % 60; t /= 60;
    int c  = t % 8;  int b = t / 8;
    const float* base = x + ((size_t)(b*8 + c)*HH + py*5)*WW + px*5;
    float s = 0.f;
    #pragma unroll
    for (int r = 0; r < 5; r++)
        #pragma unroll
        for (int q = 0; q < 5; q++) s += base[r*WW + q];
    p5f[i] = s * (1.0f/25.0f);
}
__global__ void k_poolrest() {
    int i = blockIdx.x * blockDim.x + threadIdx.x;
    if (i < 32*8*30*30) {
        int px = i % 30; int t = i / 30;
        int py = t % 30; t /= 30;
        int c  = t % 8;  int b = t / 8;
        const float* base = p5f + ((b*8 + c)*60 + py*2)*60 + px*2;
        p10f[i] = (base[0] + base[1] + base[60] + base[61]) * 0.25f;
    }
    int j = i - 32*8*30*30;
    if (j >= 0 && j < 32*8*20*20) {
        int px = j % 20; int t = j / 20;
        int py = t % 20; t /= 20;
        int c  = t % 8;  int b = t / 8;
        const float* base = p5f + ((b*8 + c)*60 + py*3)*60 + px*3;
        float s = 0.f;
        #pragma unroll
        for (int r = 0; r < 3; r++)
            #pragma unroll
            for (int q = 0; q < 3; q++) s += base[r*60 + q];
        p15f[j] = s * (1.0f/9.0f);
    }
}

// ---------------- weight fragment prep ----------------
// b-frag word = (bf16(k_odd)<<16) | bf16(k_even); thread t: n = nt*8 + t/4,
// k_even = step*16 + (t%4)*2 + r*8.
__device__ __forceinline__ float w1_val(int n, int k,
        const float* w5, const float* w10, const float* w15) {
    int a = k / 9, tap = k % 9;
    if (n < 8) {
        if (a < 16) return w5[(n*16 + a)*9 + tap];
    } else if (n < 16) {
        int ic = (a < 8) ? a : ((a >= 16 && a < 24) ? a - 8 : -1);
        if (ic >= 0) return w10[((n-8)*16 + ic)*9 + tap];
    } else {
        int ic = (a < 8) ? a : ((a >= 24) ? a - 16 : -1);
        if (ic >= 0) return w15[((n-16)*16 + ic)*9 + tap];
    }
    return 0.f;
}
__global__ void k_prepw(const float* __restrict__ w5,  const float* __restrict__ w10,
                        const float* __restrict__ w15, const float* __restrict__ gw,
                        const float* __restrict__ mw) {
    int tid = blockIdx.x * blockDim.x + threadIdx.x;
    for (int e = tid; e < STEPS1*NT1*2*32*2; e += blockDim.x * gridDim.x) {
        int r = e & 1; int t = (e >> 1) & 31; int sp = (e >> 6) & 1;
        int nt = (e >> 7) % NT1; int step = (e >> 7) / NT1;
        int n = nt*8 + t/4;
        int k0 = step*16 + (t & 3)*2 + r*8;
        float v0 = w1_val(n, k0, w5, w10, w15);
        float v1 = w1_val(n, k0+1, w5, w10, w15);
        u32 w;
        if (sp == 0) {
            w = ((u32)__bfloat16_as_ushort(__float2bfloat16(v1)) << 16)
              |  (u32)__bfloat16_as_ushort(__float2bfloat16(v0));
        } else {
            float h0 = __bfloat162float(__float2bfloat16(v0));
            float h1 = __bfloat162float(__float2bfloat16(v1));
            w = ((u32)__bfloat16_as_ushort(__float2bfloat16(v1 - h1)) << 16)
              |  (u32)__bfloat16_as_ushort(__float2bfloat16(v0 - h0));
        }
        bfrag1[e] = w;
    }
    for (int e = tid; e < STEPS2*NT2*2*32*2; e += blockDim.x * gridDim.x) {
        int r = e & 1; int t = (e >> 1) & 31; int sp = (e >> 6) & 1;
        int nt = (e >> 7) % NT2; int step = (e >> 7) / NT2;
        int n = nt*8 + t/4;
        int k0 = step*16 + (t & 3)*2 + r*8;
        float v0 = 0.f, v1 = 0.f;
        if (k0 < K2R)
            v0 = (n < 8) ? gw[(n*24 + k0/9)*9 + k0%9] : mw[((n-8)*24 + k0/9)*9 + k0%9];
        int k1 = k0 + 1;
        if (k1 < K2R)
            v1 = (n < 8) ? gw[(n*24 + k1/9)*9 + k1%9] : mw[((n-8)*24 + k1/9)*9 + k1%9];
        u32 w;
        if (sp == 0) {
            w = ((u32)__bfloat16_as_ushort(__float2bfloat16(v1)) << 16)
              |  (u32)__bfloat16_as_ushort(__float2bfloat16(v0));
        } else {
            float h0 = __bfloat162float(__float2bfloat16(v0));
            float h1 = __bfloat162float(__float2bfloat16(v1));
            w = ((u32)__bfloat16_as_ushort(__float2bfloat16(v1 - h1)) << 16)
              |  (u32)__bfloat16_as_ushort(__float2bfloat16(v0 - h0));
        }
        bfrag2[e] = w;
    }
}

// ---------------- conv1: x||up5||up10||up15 -> g_in (packed) ----------------
// smem: tile[32*612] u32 | bfrag 6912 | koff 288 | bias 24f
__global__ void __launch_bounds__(256, 2)
k_conv1(const float* __restrict__ x,
        const float* __restrict__ b5, const float* __restrict__ b10,
        const float* __restrict__ b15) {
    extern __shared__ u32 sm[];
    u32* tile = sm;                         // 19584
    u32* bsm  = sm + 32*PLANE;              // 6912
    int* koffs = (int*)(bsm + STEPS1*NT1*2*32*2);  // 288
    float* bias = (float*)(koffs + K1);     // 24

    int tid = threadIdx.x;
    int b  = blockIdx.z;
    int x0 = blockIdx.x * TW, y0 = blockIdx.y * TH;

    // in-tile load (fp32 sources -> packed split)
    for (int i = tid; i < 32*PLANE; i += 256) {
        int c = i / PLANE; int rem = i % PLANE;
        int ty = rem / INW, tx = rem % INW;
        int gy = y0 - 1 + ty, gx = x0 - 1 + tx;
        float v = 0.f;
        if (gy >= 0 && gy < HH && gx >= 0 && gx < WW) {
            if (c < 8)       v = x[((size_t)(b*8 + c)*HH + gy)*WW + gx];
            else if (c < 16) v = p5f [((b*8 + c - 8 )*60 + gy/5 )*60 + gx/5 ];
            else if (c < 24) v = p10f[((b*8 + c - 16)*30 + gy/10)*30 + gx/10];
            else             v = p15f[((b*8 + c - 24)*20 + gy/15)*20 + gx/15];
        }
        tile[i] = pack_split(v);
    }
    for (int i = tid; i < STEPS1*NT1*2*32*2; i += 256) bsm[i] = bfrag1[i];
    for (int k = tid; k < K1; k += 256)
        koffs[k] = (k/9)*PLANE + ((k%9)/3)*INW + (k%3);
    if (tid < 24)
        bias[tid] = (tid < 8) ? b5[tid] : (tid < 16 ? b10[tid-8] : b15[tid-16]);
    __syncthreads();

    int lane = tid & 31, w = tid >> 5;
    int g = lane >> 2, tg = lane & 3;
    int s = w >> 2, wr = w & 3;

    for (int p = 0; p < 2; p++) {
        int ry0 = wr*4 + p*2;                 // rows ry0, ry0+1
        int baseA = ry0*INW + s*16 + g;
        float d[2][NT1][4];
        #pragma unroll
        for (int j = 0; j < 2; j++)
            #pragma unroll
            for (int nt = 0; nt < NT1; nt++)
                #pragma unroll
                for (int q = 0; q < 4; q++) d[j][nt][q] = 0.f;

        for (int step = 0; step < STEPS1; step++) {
            int kb = step*16 + 2*tg;
            int o0 = koffs[kb], o1 = koffs[kb+1], o2 = koffs[kb+8], o3 = koffs[kb+9];
            u32 ah[2][4], al[2][4];
            #pragma unroll
            for (int j = 0; j < 2; j++) {
                int ba = baseA + j*INW;
                u32 e00 = tile[ba + o0],   e01 = tile[ba + o1];
                u32 e02 = tile[ba + o2],   e03 = tile[ba + o3];
                u32 e10 = tile[ba+8 + o0], e11 = tile[ba+8 + o1];
                u32 e12 = tile[ba+8 + o2], e13 = tile[ba+8 + o3];
                ah[j][0] = __byte_perm(e00, e01, 0x7632);
                ah[j][1] = __byte_perm(e10, e11, 0x7632);
                ah[j][2] = __byte_perm(e02, e03, 0x7632);
                ah[j][3] = __byte_perm(e12, e13, 0x7632);
                al[j][0] = __byte_perm(e00, e01, 0x5410);
                al[j][1] = __byte_perm(e10, e11, 0x5410);
                al[j][2] = __byte_perm(e02, e03, 0x5410);
                al[j][3] = __byte_perm(e12, e13, 0x5410);
            }
            #pragma unroll
            for (int nt = 0; nt < NT1; nt++) {
                int bi = ((step*NT1 + nt)*2)*64 + lane*2;
                uint2 bh = *reinterpret_cast<const uint2*>(&bsm[bi]);
                uint2 bl = *reinterpret_cast<const uint2*>(&bsm[bi + 64]);
                #pragma unroll
                for (int j = 0; j < 2; j++) {
                    mma_bf16(d[j][nt], ah[j][0], ah[j][1], ah[j][2], ah[j][3], bh.x, bh.y);
                    mma_bf16(d[j][nt], ah[j][0], ah[j][1], ah[j][2], ah[j][3], bl.x, bl.y);
                    mma_bf16(d[j][nt], al[j][0], al[j][1], al[j][2], al[j][3], bh.x, bh.y);
                }
            }
        }

        // epilogue: +bias, split-pack, store to g_pk
        #pragma unroll
        for (int j = 0; j < 2; j++) {
            int py = y0 + ry0 + j;
            if (py >= HH) continue;
            int px0 = x0 + s*16 + g;
            #pragma unroll
            for (int nt = 0; nt < NT1; nt++) {
                int oc = nt*8 + 2*tg;
                float bv0 = bias[oc], bv1 = bias[oc+1];
                size_t r0 = ((size_t)(b*24 + oc  )*HH + py)*WW;
                size_t r1 = ((size_t)(b*24 + oc+1)*HH + py)*WW;
                if (px0 < WW) {
                    g_pk[r0 + px0] = pack_split(d[j][nt][0] + bv0);
                    g_pk[r1 + px0] = pack_split(d[j][nt][1] + bv1);
                }
                if (px0 + 8 < WW) {
                    g_pk[r0 + px0+8] = pack_split(d[j][nt][2] + bv0);
                    g_pk[r1 + px0+8] = pack_split(d[j][nt][3] + bv1);
                }
            }
        }
    }
}

// ---------------- conv2: gated pair + BN partials ----------------
// smem: tile[24*612] | bfrag 3584 | koff 224 | bias 16f | red 128f
__global__ void __launch_bounds__(256, 2)
k_conv2(const float* __restrict__ gb, const float* __restrict__ mb,
        float* __restrict__ out) {
    extern __shared__ u32 sm[];
    u32* tile = sm;                          // 14688
    u32* bsm  = sm + 24*PLANE;               // 3584
    int* koffs = (int*)(bsm + STEPS2*NT2*2*32*2);  // 224
    float* bias = (float*)(koffs + K2);      // 16
    float* red  = bias + 16;                 // 128

    int tid = threadIdx.x;
    int b  = blockIdx.z;
    int x0 = blockIdx.x * TW, y0 = blockIdx.y * TH;

    for (int i = tid; i < 24*PLANE; i += 256) {
        int c = i / PLANE; int rem = i % PLANE;
        int ty = rem / INW, tx = rem % INW;
        int gy = y0 - 1 + ty, gx = x0 - 1 + tx;
        u32 v = 0u;
        if (gy >= 0 && gy < HH && gx >= 0 && gx < WW)
            v = g_pk[((size_t)(b*24 + c)*HH + gy)*WW + gx];
        tile[i] = v;
    }
    for (int i = tid; i < STEPS2*NT2*2*32*2; i += 256) bsm[i] = bfrag2[i];
    for (int k = tid; k < K2; k += 256)
        koffs[k] = (k < K2R) ? (k/9)*PLANE + ((k%9)/3)*INW + (k%3) : 0;
    if (tid < 16) bias[tid] = (tid < 8) ? gb[tid] : mb[tid-8];
    __syncthreads();

    int lane = tid & 31, w = tid >> 5;
    int g = lane >> 2, tg = lane & 3;
    int s = w >> 2, wr = w & 3;

    float s0 = 0.f, s1 = 0.f, q0 = 0.f, q1 = 0.f;  // stats for oc 2tg, 2tg+1

    for (int p = 0; p < 2; p++) {
        int ry0 = wr*4 + p*2;
        int baseA = ry0*INW + s*16 + g;
        float d[2][NT2][4];
        #pragma unroll
        for (int j = 0; j < 2; j++)
            #pragma unroll
            for (int nt = 0; nt < NT2; nt++)
                #pragma unroll
                for (int q = 0; q < 4; q++) d[j][nt][q] = 0.f;

        for (int step = 0; step < STEPS2; step++) {
            int kb = step*16 + 2*tg;
            int o0 = koffs[kb], o1 = koffs[kb+1], o2 = koffs[kb+8], o3 = koffs[kb+9];
            u32 ah[2][4], al[2][4];
            #pragma unroll
            for (int j = 0; j < 2; j++) {
                int ba = baseA + j*INW;
                u32 e00 = tile[ba + o0],   e01 = tile[ba + o1];
                u32 e02 = tile[ba + o2],   e03 = tile[ba + o3];
                u32 e10 = tile[ba+8 + o0], e11 = tile[ba+8 + o1];
                u32 e12 = tile[ba+8 + o2], e13 = tile[ba+8 + o3];
                ah[j][0] = __byte_perm(e00, e01, 0x7632);
                ah[j][1] = __byte_perm(e10, e11, 0x7632);
                ah[j][2] = __byte_perm(e02, e03, 0x7632);
                ah[j][3] = __byte_perm(e12, e13, 0x7632);
                al[j][0] = __byte_perm(e00, e01, 0x5410);
                al[j][1] = __byte_perm(e10, e11, 0x5410);
                al[j][2] = __byte_perm(e02, e03, 0x5410);
                al[j][3] = __byte_perm(e12, e13, 0x5410);
            }
            #pragma unroll
            for (int nt = 0; nt < NT2; nt++) {
                int bi = ((step*NT2 + nt)*2)*64 + lane*2;
                uint2 bh = *reinterpret_cast<const uint2*>(&bsm[bi]);
                uint2 bl = *reinterpret_cast<const uint2*>(&bsm[bi + 64]);
                #pragma unroll
                for (int j = 0; j < 2; j++) {
                    mma_bf16(d[j][nt], ah[j][0], ah[j][1], ah[j][2], ah[j][3], bh.x, bh.y);
                    mma_bf16(d[j][nt], ah[j][0], ah[j][1], ah[j][2], ah[j][3], bl.x, bl.y);
                    mma_bf16(d[j][nt], al[j][0], al[j][1], al[j][2], al[j][3], bh.x, bh.y);
                }
            }
        }

        // epilogue: gate, store, stats
        int oc0 = 2*tg;
        float bg0 = bias[oc0], bg1 = bias[oc0+1];
        float bm0 = bias[8+oc0], bm1 = bias[8+oc0+1];
        #pragma unroll
        for (int j = 0; j < 2; j++) {
            int py = y0 + ry0 + j;
            bool vy = (py < HH);
            int px0 = x0 + s*16 + g;
            size_t r0 = ((size_t)(b*8 + oc0  )*HH + py)*WW;
            size_t r1 = ((size_t)(b*8 + oc0+1)*HH + py)*WW;
            #pragma unroll
            for (int h = 0; h < 2; h++) {       // rows g (h=0) and g+8 (h=1)
                int px = px0 + h*8;
                bool vld = vy && (px < WW);
                float ga = d[j][0][2*h]   + bg0;
                float gb_ = d[j][0][2*h+1] + bg1;
                float ma = d[j][1][2*h]   + bm0;
                float mb_ = d[j][1][2*h+1] + bm1;
                float y0v = ga / (1.f + __expf(-ma));
                float y1v = gb_ / (1.f + __expf(-mb_));
                if (vld) {
                    out[r0 + px] = y0v;
                    out[r1 + px] = y1v;
                    s0 += y0v; q0 += y0v*y0v;
                    s1 += y1v; q1 += y1v*y1v;
                }
            }
        }
    }

    // reduce over g bits (lanes xor 4,8,16)
    #pragma unroll
    for (int dlt = 4; dlt < 32; dlt <<= 1) {
        s0 += __shfl_xor_sync(0xffffffffu, s0, dlt);
        s1 += __shfl_xor_sync(0xffffffffu, s1, dlt);
        q0 += __shfl_xor_sync(0xffffffffu, q0, dlt);
        q1 += __shfl_xor_sync(0xffffffffu, q1, dlt);
    }
    if (g == 0) {
        red[w*16 + 2*tg]     = s0;
        red[w*16 + 2*tg + 1] = s1;
        red[w*16 + 8 + 2*tg]     = q0;
        red[w*16 + 8 + 2*tg + 1] = q1;
    }
    __syncthreads();
    if (tid < 16) {
        float t = 0.f;
        #pragma unroll
        for (int w2 = 0; w2 < 8; w2++) t += red[w2*16 + tid];
        int blin = (b*GY + blockIdx.y)*GX + blockIdx.x;
        part_buf[blin*16 + tid] = t;
    }
}

// ---------------- BN stats (deterministic, double) ----------------
__global__ void k_stats(const float* __restrict__ gamma, const float* __restrict__ beta) {
    __shared__ double red[16*9];
    int tid = threadIdx.x;
    int wid = tid >> 5, lane = tid & 31;
    double acc[16];
    #pragma unroll
    for (int v = 0; v < 16; v++) acc[v] = 0.0;
    for (int i = tid; i < NBLK; i += 256) {
        #pragma unroll
        for (int v = 0; v < 16; v++) acc[v] += (double)part_buf[i*16 + v];
    }
    #pragma unroll
    for (int v = 0; v < 16; v++)
        for (int d = 16; d > 0; d >>= 1)
            acc[v] += __shfl_xor_sync(0xffffffffu, acc[v], d);
    if (lane == 0) {
        #pragma unroll
        for (int v = 0; v < 16; v++) red[wid*16 + v] = acc[v];
    }
    __syncthreads();
    if (tid < 16) {
        double ssum = 0.0;
        #pragma unroll
        for (int w = 0; w < 8; w++) ssum += red[w*16 + tid];
        red[128 + tid] = ssum;
    }
    __syncthreads();
    if (tid < 8) {
        const double N = 2880000.0;
        double mean = red[128 + tid] / N;
        double ex2  = red[136 + tid] / N;
        double var  = ex2 - mean * mean;
        double scale = (double)gamma[tid] / sqrt(var + 1e-5);
        double shift = (double)beta[tid] - mean * scale;
        bn_buf[tid]     = (float)scale;
        bn_buf[8 + tid] = (float)shift;
    }
}

// ---------------- normalize ----------------
__global__ void k_norm(float* __restrict__ out) {
    int i = blockIdx.x * blockDim.x + threadIdx.x;
    if (i >= 5760000) return;
    int c = (i / 22500) & 7;
    float sc = bn_buf[c], sh = bn_buf[8 + c];
    float4 v = reinterpret_cast<float4*>(out)[i];
    v.x = v.x * sc + sh;
    v.y = v.y * sc + sh;
    v.z = v.z * sc + sh;
    v.w = v.w * sc + sh;
    reinterpret_cast<float4*>(out)[i] = v;
}

// ---------------- launch ----------------
extern "C" void kernel_launch(void* const* d_in, const int* in_sizes, int n_in,
                              void* d_out, int out_size) {
    const float* x    = (const float*)d_in[0];
    const float* w5   = (const float*)d_in[1];
    const float* b5   = (const float*)d_in[2];
    const float* w10  = (const float*)d_in[3];
    const float* b10  = (const float*)d_in[4];
    const float* w15  = (const float*)d_in[5];
    const float* b15  = (const float*)d_in[6];
    const float* gw   = (const float*)d_in[7];
    const float* gb   = (const float*)d_in[8];
    const float* mw   = (const float*)d_in[9];
    const float* mb   = (const float*)d_in[10];
    const float* gamma= (const float*)d_in[11];
    const float* beta = (const float*)d_in[12];
    float* out = (float*)d_out;

    const int smem1 = (32*PLANE + STEPS1*NT1*2*32*2 + K1 + 24 + 8) * 4;
    const int smem2 = (24*PLANE + STEPS2*NT2*2*32*2 + K2 + 16 + 128 + 8) * 4;
    cudaFuncSetAttribute(k_conv1, cudaFuncAttributeMaxDynamicSharedMemorySize, smem1);
    cudaFuncSetAttribute(k_conv2, cudaFuncAttributeMaxDynamicSharedMemorySize, smem2);

    k_pool5   <<<(921600 + 255) / 256, 256>>>(x);
    k_poolrest<<<(332800 + 255) / 256, 256>>>();
    k_prepw   <<<32, 256>>>(w5, w10, w15, gw, mw);

    dim3 grid(GX, GY, 32);
    k_conv1<<<grid, 256, smem1>>>(x, b5, b10, b15);
    k_conv2<<<grid, 256, smem2>>>(gb, mb, out);

    k_stats<<<1, 256>>>(gamma, beta);
    k_norm <<<(5760000 + 255) / 256, 256>>>(out);
}

// round 10
// speedup vs baseline: 1.6012x; 1.3870x over previous
#include <cuda_runtime.h>
#include <cuda_bf16.h>
#include <cstdint>

typedef unsigned int u32;

#define HH 300
#define WW 300

// output tile geometry
#define TW 32
#define TH 16
#define INW 34
#define INH 18
#define PLANE (INH*INW)   // 612
#define PPAD 616          // padded pixel stride (616 % 32 == 8 -> conflict-free)
#define GX 10
#define GY 19
#define NBLK (GX*GY*32)   // 6080

// conv1: per tap, per branch: K=16 = [x 8ch | up_b 8ch], N=8. 27 (branch,tap) frags.
#define NFRAG1 27
// conv2: K = 216 padded 224
#define K2 224
#define K2R 216
#define STEPS2 14
#define NT2 2

// ---------------- device scratch ----------------
__device__ u32   g_pk[32u*24u*HH*WW];        // packed (hi<<16|lo) bf16 pairs
__device__ float p5f[32*8*60*60];
__device__ float p10f[32*8*30*30];
__device__ float p15f[32*8*20*20];
__device__ u32   bfrag1[NFRAG1*128];         // 3456
__device__ u32   bfrag2[STEPS2*NT2*2*32*2];  // 3584
__device__ float part_buf[NBLK*16];
__device__ float bn_buf[16];

// ---------------- helpers ----------------
__device__ __forceinline__ u32 pack_split(float v) {
    __nv_bfloat16 h = __float2bfloat16(v);
    float hf = __bfloat162float(h);
    __nv_bfloat16 l = __float2bfloat16(v - hf);
    return ((u32)__bfloat16_as_ushort(h) << 16) | (u32)__bfloat16_as_ushort(l);
}
__device__ __forceinline__ void mma_bf16(float* d, u32 a0, u32 a1, u32 a2, u32 a3,
                                         u32 b0, u32 b1) {
    asm volatile(
        "mma.sync.aligned.m16n8k16.row.col.f32.bf16.bf16.f32 "
        "{%0,%1,%2,%3},{%4,%5,%6,%7},{%8,%9},{%0,%1,%2,%3};"
        : "+f"(d[0]), "+f"(d[1]), "+f"(d[2]), "+f"(d[3])
        : "r"(a0), "r"(a1), "r"(a2), "r"(a3), "r"(b0), "r"(b1));
}

// ---------------- pools (fp32) ----------------
__global__ void k_pool5(const float* __restrict__ x) {
    int i = blockIdx.x * blockDim.x + threadIdx.x;
    if (i >= 32*8*60*60) return;
    int px = i % 60; int t = i / 60;
    int py = t % 60; t /= 60;
    int c  = t % 8;  int b = t / 8;
    const float* base = x + ((size_t)(b*8 + c)*HH + py*5)*WW + px*5;
    float s = 0.f;
    #pragma unroll
    for (int r = 0; r < 5; r++)
        #pragma unroll
        for (int q = 0; q < 5; q++) s += base[r*WW + q];
    p5f[i] = s * (1.0f/25.0f);
}
__global__ void k_poolrest() {
    int i = blockIdx.x * blockDim.x + threadIdx.x;
    if (i < 32*8*30*30) {
        int px = i % 30; int t = i / 30;
        int py = t % 30; t /= 30;
        int c  = t % 8;  int b = t / 8;
        const float* base = p5f + ((b*8 + c)*60 + py*2)*60 + px*2;
        p10f[i] = (base[0] + base[1] + base[60] + base[61]) * 0.25f;
    }
    int j = i - 32*8*30*30;
    if (j >= 0 && j < 32*8*20*20) {
        int px = j % 20; int t = j / 20;
        int py = t % 20; t /= 20;
        int c  = t % 8;  int b = t / 8;
        const float* base = p5f + ((b*8 + c)*60 + py*3)*60 + px*3;
        float s = 0.f;
        #pragma unroll
        for (int r = 0; r < 3; r++)
            #pragma unroll
            for (int q = 0; q < 3; q++) s += base[r*60 + q];
        p15f[j] = s * (1.0f/9.0f);
    }
}

// ---------------- weight fragment prep ----------------
__global__ void k_prepw(const float* __restrict__ w5,  const float* __restrict__ w10,
                        const float* __restrict__ w15, const float* __restrict__ gw,
                        const float* __restrict__ mw) {
    int tid = blockIdx.x * blockDim.x + threadIdx.x;
    for (int e = tid; e < NFRAG1*128; e += blockDim.x * gridDim.x) {
        int blk = e >> 7;
        int rem = e & 127;
        int sp = rem >> 6;
        int lane = (rem & 63) >> 1;
        int r = rem & 1;
        int br = blk / 9, tap = blk % 9;
        const float* w = (br == 0) ? w5 : (br == 1 ? w10 : w15);
        int n = lane >> 2;
        int k0 = (lane & 3)*2 + r*8;
        float v0 = w[(n*16 + k0    )*9 + tap];
        float v1 = w[(n*16 + k0 + 1)*9 + tap];
        u32 word;
        if (sp == 0) {
            word = ((u32)__bfloat16_as_ushort(__float2bfloat16(v1)) << 16)
                 |  (u32)__bfloat16_as_ushort(__float2bfloat16(v0));
        } else {
            float h0 = __bfloat162float(__float2bfloat16(v0));
            float h1 = __bfloat162float(__float2bfloat16(v1));
            word = ((u32)__bfloat16_as_ushort(__float2bfloat16(v1 - h1)) << 16)
                 |  (u32)__bfloat16_as_ushort(__float2bfloat16(v0 - h0));
        }
        bfrag1[e] = word;
    }
    for (int e = tid; e < STEPS2*NT2*2*32*2; e += blockDim.x * gridDim.x) {
        int r = e & 1; int t = (e >> 1) & 31; int sp = (e >> 6) & 1;
        int nt = (e >> 7) % NT2; int step = (e >> 7) / NT2;
        int n = nt*8 + t/4;
        int k0 = step*16 + (t & 3)*2 + r*8;
        float v0 = 0.f, v1 = 0.f;
        if (k0 < K2R)
            v0 = (n < 8) ? gw[(n*24 + k0/9)*9 + k0%9] : mw[((n-8)*24 + k0/9)*9 + k0%9];
        int k1 = k0 + 1;
        if (k1 < K2R)
            v1 = (n < 8) ? gw[(n*24 + k1/9)*9 + k1%9] : mw[((n-8)*24 + k1/9)*9 + k1%9];
        u32 w;
        if (sp == 0) {
            w = ((u32)__bfloat16_as_ushort(__float2bfloat16(v1)) << 16)
              |  (u32)__bfloat16_as_ushort(__float2bfloat16(v0));
        } else {
            float h0 = __bfloat162float(__float2bfloat16(v0));
            float h1 = __bfloat162float(__float2bfloat16(v1));
            w = ((u32)__bfloat16_as_ushort(__float2bfloat16(v1 - h1)) << 16)
              |  (u32)__bfloat16_as_ushort(__float2bfloat16(v0 - h0));
        }
        bfrag2[e] = w;
    }
}

// ---------------- conv1: branch GEMMs, interleaved pre-split tile ----------------
// smem: tileH[16*616] | tileL[16*616] | bsm[3456] | bias[24]
__global__ void __launch_bounds__(256, 2)
k_conv1(const float* __restrict__ x,
        const float* __restrict__ b5, const float* __restrict__ b10,
        const float* __restrict__ b15) {
    extern __shared__ u32 sm[];
    u32* tileH = sm;                      // 9856
    u32* tileL = sm + 16*PPAD;            // 9856
    u32* bsm   = sm + 32*PPAD;            // 3456
    float* bias = (float*)(bsm + NFRAG1*128);  // 24

    int tid = threadIdx.x;
    int b  = blockIdx.z;
    int x0 = blockIdx.x * TW, y0 = blockIdx.y * TH;

    // tile load: c2 pairs of union channels [x(0-3) | u5(4-7) | u10(8-11) | u15(12-15)]
    for (int i = tid; i < 16*PLANE; i += 256) {
        int c2 = i / PLANE, pix = i % PLANE;
        int ty = pix / INW, tx = pix % INW;
        int gy = y0 - 1 + ty, gx = x0 - 1 + tx;
        float v0 = 0.f, v1 = 0.f;
        if (gy >= 0 && gy < HH && gx >= 0 && gx < WW) {
            if (c2 < 4) {
                const float* p = x + ((size_t)(b*8 + 2*c2)*HH + gy)*WW + gx;
                v0 = p[0]; v1 = p[(size_t)HH*WW];
            } else if (c2 < 8) {
                const float* p = p5f + ((b*8 + 2*(c2-4))*60 + gy/5)*60 + gx/5;
                v0 = p[0]; v1 = p[3600];
            } else if (c2 < 12) {
                const float* p = p10f + ((b*8 + 2*(c2-8))*30 + gy/10)*30 + gx/10;
                v0 = p[0]; v1 = p[900];
            } else {
                const float* p = p15f + ((b*8 + 2*(c2-12))*20 + gy/15)*20 + gx/15;
                v0 = p[0]; v1 = p[400];
            }
        }
        __nv_bfloat162 Hh = __floats2bfloat162_rn(v0, v1);
        float2 hf = __bfloat1622float2(Hh);
        __nv_bfloat162 Ll = __floats2bfloat162_rn(v0 - hf.x, v1 - hf.y);
        tileH[c2*PPAD + pix] = *reinterpret_cast<u32*>(&Hh);
        tileL[c2*PPAD + pix] = *reinterpret_cast<u32*>(&Ll);
    }
    for (int i = tid; i < NFRAG1*128; i += 256) bsm[i] = bfrag1[i];
    if (tid < 24)
        bias[tid] = (tid < 8) ? b5[tid] : (tid < 16 ? b10[tid-8] : b15[tid-16]);
    __syncthreads();

    int lane = tid & 31, w = tid >> 5;
    int g = lane >> 2, tg = lane & 3;
    int s = w >> 2, wr = w & 3;
    const int xrow = tg * PPAD;

    #pragma unroll 1
    for (int p = 0; p < 2; p++) {
        int ry0 = wr*4 + p*2;
        int base0 = ry0*INW + s*16 + g;
        float d[2][3][4];
        #pragma unroll
        for (int j = 0; j < 2; j++)
            #pragma unroll
            for (int br = 0; br < 3; br++)
                #pragma unroll
                for (int q = 0; q < 4; q++) d[j][br][q] = 0.f;

        #pragma unroll
        for (int tap = 0; tap < 9; tap++) {
            const int koff = (tap/3)*INW + (tap%3);
            uint2 bh[3], bl[3];
            #pragma unroll
            for (int br = 0; br < 3; br++) {
                int bb = (br*9 + tap)*128 + lane*2;
                bh[br] = *reinterpret_cast<const uint2*>(&bsm[bb]);
                bl[br] = *reinterpret_cast<const uint2*>(&bsm[bb + 64]);
            }
            #pragma unroll
            for (int j = 0; j < 2; j++) {
                int ap = base0 + j*INW + koff;
                u32 xh0 = tileH[xrow + ap], xh1 = tileH[xrow + ap + 8];
                u32 xl0 = tileL[xrow + ap], xl1 = tileL[xrow + ap + 8];
                #pragma unroll
                for (int br = 0; br < 3; br++) {
                    int ur = (4 + 4*br + tg)*PPAD + ap;
                    u32 uh0 = tileH[ur], uh1 = tileH[ur + 8];
                    u32 ul0 = tileL[ur], ul1 = tileL[ur + 8];
                    mma_bf16(d[j][br], xh0, xh1, uh0, uh1, bh[br].x, bh[br].y);
                    mma_bf16(d[j][br], xh0, xh1, uh0, uh1, bl[br].x, bl[br].y);
                    mma_bf16(d[j][br], xl0, xl1, ul0, ul1, bh[br].x, bh[br].y);
                }
            }
        }

        // epilogue: +bias, split-pack, store to g_pk
        #pragma unroll
        for (int j = 0; j < 2; j++) {
            int py = y0 + ry0 + j;
            if (py >= HH) continue;
            int px0 = x0 + s*16 + g;
            #pragma unroll
            for (int br = 0; br < 3; br++) {
                int oc = br*8 + 2*tg;
                float bv0 = bias[oc], bv1 = bias[oc+1];
                size_t r0 = ((size_t)(b*24 + oc  )*HH + py)*WW;
                size_t r1 = ((size_t)(b*24 + oc+1)*HH + py)*WW;
                if (px0 < WW) {
                    g_pk[r0 + px0] = pack_split(d[j][br][0] + bv0);
                    g_pk[r1 + px0] = pack_split(d[j][br][1] + bv1);
                }
                if (px0 + 8 < WW) {
                    g_pk[r0 + px0+8] = pack_split(d[j][br][2] + bv0);
                    g_pk[r1 + px0+8] = pack_split(d[j][br][3] + bv1);
                }
            }
        }
    }
}

// ---------------- conv2: gated pair + BN partials ----------------
__global__ void __launch_bounds__(256, 2)
k_conv2(const float* __restrict__ gb, const float* __restrict__ mb,
        float* __restrict__ out) {
    extern __shared__ u32 sm[];
    u32* tile = sm;                          // 14688
    u32* bsm  = sm + 24*PLANE;               // 3584
    int* koffs = (int*)(bsm + STEPS2*NT2*2*32*2);  // 224
    float* bias = (float*)(koffs + K2);      // 16
    float* red  = bias + 16;                 // 128

    int tid = threadIdx.x;
    int b  = blockIdx.z;
    int x0 = blockIdx.x * TW, y0 = blockIdx.y * TH;

    for (int i = tid; i < 24*PLANE; i += 256) {
        int c = i / PLANE; int rem = i % PLANE;
        int ty = rem / INW, tx = rem % INW;
        int gy = y0 - 1 + ty, gx = x0 - 1 + tx;
        u32 v = 0u;
        if (gy >= 0 && gy < HH && gx >= 0 && gx < WW)
            v = g_pk[((size_t)(b*24 + c)*HH + gy)*WW + gx];
        tile[i] = v;
    }
    for (int i = tid; i < STEPS2*NT2*2*32*2; i += 256) bsm[i] = bfrag2[i];
    for (int k = tid; k < K2; k += 256)
        koffs[k] = (k < K2R) ? (k/9)*PLANE + ((k%9)/3)*INW + (k%3) : 0;
    if (tid < 16) bias[tid] = (tid < 8) ? gb[tid] : mb[tid-8];
    __syncthreads();

    int lane = tid & 31, w = tid >> 5;
    int g = lane >> 2, tg = lane & 3;
    int s = w >> 2, wr = w & 3;

    float s0 = 0.f, s1 = 0.f, q0 = 0.f, q1 = 0.f;

    for (int p = 0; p < 2; p++) {
        int ry0 = wr*4 + p*2;
        int baseA = ry0*INW + s*16 + g;
        float d[2][NT2][4];
        #pragma unroll
        for (int j = 0; j < 2; j++)
            #pragma unroll
            for (int nt = 0; nt < NT2; nt++)
                #pragma unroll
                for (int q = 0; q < 4; q++) d[j][nt][q] = 0.f;

        for (int step = 0; step < STEPS2; step++) {
            int kb = step*16 + 2*tg;
            int o0 = koffs[kb], o1 = koffs[kb+1], o2 = koffs[kb+8], o3 = koffs[kb+9];
            u32 ah[2][4], al[2][4];
            #pragma unroll
            for (int j = 0; j < 2; j++) {
                int ba = baseA + j*INW;
                u32 e00 = tile[ba + o0],   e01 = tile[ba + o1];
                u32 e02 = tile[ba + o2],   e03 = tile[ba + o3];
                u32 e10 = tile[ba+8 + o0], e11 = tile[ba+8 + o1];
                u32 e12 = tile[ba+8 + o2], e13 = tile[ba+8 + o3];
                ah[j][0] = __byte_perm(e00, e01, 0x7632);
                ah[j][1] = __byte_perm(e10, e11, 0x7632);
                ah[j][2] = __byte_perm(e02, e03, 0x7632);
                ah[j][3] = __byte_perm(e12, e13, 0x7632);
                al[j][0] = __byte_perm(e00, e01, 0x5410);
                al[j][1] = __byte_perm(e10, e11, 0x5410);
                al[j][2] = __byte_perm(e02, e03, 0x5410);
                al[j][3] = __byte_perm(e12, e13, 0x5410);
            }
            #pragma unroll
            for (int nt = 0; nt < NT2; nt++) {
                int bi = ((step*NT2 + nt)*2)*64 + lane*2;
                uint2 bh = *reinterpret_cast<const uint2*>(&bsm[bi]);
                uint2 bl = *reinterpret_cast<const uint2*>(&bsm[bi + 64]);
                #pragma unroll
                for (int j = 0; j < 2; j++) {
                    mma_bf16(d[j][nt], ah[j][0], ah[j][1], ah[j][2], ah[j][3], bh.x, bh.y);
                    mma_bf16(d[j][nt], ah[j][0], ah[j][1], ah[j][2], ah[j][3], bl.x, bl.y);
                    mma_bf16(d[j][nt], al[j][0], al[j][1], al[j][2], al[j][3], bh.x, bh.y);
                }
            }
        }

        int oc0 = 2*tg;
        float bg0 = bias[oc0], bg1 = bias[oc0+1];
        float bm0 = bias[8+oc0], bm1 = bias[8+oc0+1];
        #pragma unroll
        for (int j = 0; j < 2; j++) {
            int py = y0 + ry0 + j;
            bool vy = (py < HH);
            int px0 = x0 + s*16 + g;
            size_t r0 = ((size_t)(b*8 + oc0  )*HH + py)*WW;
            size_t r1 = ((size_t)(b*8 + oc0+1)*HH + py)*WW;
            #pragma unroll
            for (int h = 0; h < 2; h++) {
                int px = px0 + h*8;
                bool vld = vy && (px < WW);
                float ga = d[j][0][2*h]   + bg0;
                float gb_ = d[j][0][2*h+1] + bg1;
                float ma = d[j][1][2*h]   + bm0;
                float mb_ = d[j][1][2*h+1] + bm1;
                float y0v = ga / (1.f + __expf(-ma));
                float y1v = gb_ / (1.f + __expf(-mb_));
                if (vld) {
                    out[r0 + px] = y0v;
                    out[r1 + px] = y1v;
                    s0 += y0v; q0 += y0v*y0v;
                    s1 += y1v; q1 += y1v*y1v;
                }
            }
        }
    }

    #pragma unroll
    for (int dlt = 4; dlt < 32; dlt <<= 1) {
        s0 += __shfl_xor_sync(0xffffffffu, s0, dlt);
        s1 += __shfl_xor_sync(0xffffffffu, s1, dlt);
        q0 += __shfl_xor_sync(0xffffffffu, q0, dlt);
        q1 += __shfl_xor_sync(0xffffffffu, q1, dlt);
    }
    if (g == 0) {
        red[w*16 + 2*tg]     = s0;
        red[w*16 + 2*tg + 1] = s1;
        red[w*16 + 8 + 2*tg]     = q0;
        red[w*16 + 8 + 2*tg + 1] = q1;
    }
    __syncthreads();
    if (tid < 16) {
        float t = 0.f;
        #pragma unroll
        for (int w2 = 0; w2 < 8; w2++) t += red[w2*16 + tid];
        int blin = (b*GY + blockIdx.y)*GX + blockIdx.x;
        part_buf[blin*16 + tid] = t;
    }
}

// ---------------- BN stats (deterministic, double) ----------------
__global__ void k_stats(const float* __restrict__ gamma, const float* __restrict__ beta) {
    __shared__ double red[16*9];
    int tid = threadIdx.x;
    int wid = tid >> 5, lane = tid & 31;
    double acc[16];
    #pragma unroll
    for (int v = 0; v < 16; v++) acc[v] = 0.0;
    for (int i = tid; i < NBLK; i += 256) {
        #pragma unroll
        for (int v = 0; v < 16; v++) acc[v] += (double)part_buf[i*16 + v];
    }
    #pragma unroll
    for (int v = 0; v < 16; v++)
        for (int d = 16; d > 0; d >>= 1)
            acc[v] += __shfl_xor_sync(0xffffffffu, acc[v], d);
    if (lane == 0) {
        #pragma unroll
        for (int v = 0; v < 16; v++) red[wid*16 + v] = acc[v];
    }
    __syncthreads();
    if (tid < 16) {
        double ssum = 0.0;
        #pragma unroll
        for (int w = 0; w < 8; w++) ssum += red[w*16 + tid];
        red[128 + tid] = ssum;
    }
    __syncthreads();
    if (tid < 8) {
        const double N = 2880000.0;
        double mean = red[128 + tid] / N;
        double ex2  = red[136 + tid] / N;
        double var  = ex2 - mean * mean;
        double scale = (double)gamma[tid] / sqrt(var + 1e-5);
        double shift = (double)beta[tid] - mean * scale;
        bn_buf[tid]     = (float)scale;
        bn_buf[8 + tid] = (float)shift;
    }
}

// ---------------- normalize ----------------
__global__ void k_norm(float* __restrict__ out) {
    int i = blockIdx.x * blockDim.x + threadIdx.x;
    if (i >= 5760000) return;
    int c = (i / 22500) & 7;
    float sc = bn_buf[c], sh = bn_buf[8 + c];
    float4 v = reinterpret_cast<float4*>(out)[i];
    v.x = v.x * sc + sh;
    v.y = v.y * sc + sh;
    v.z = v.z * sc + sh;
    v.w = v.w * sc + sh;
    reinterpret_cast<float4*>(out)[i] = v;
}

// ---------------- launch ----------------
extern "C" void kernel_launch(void* const* d_in, const int* in_sizes, int n_in,
                              void* d_out, int out_size) {
    const float* x    = (const float*)d_in[0];
    const float* w5   = (const float*)d_in[1];
    const float* b5   = (const float*)d_in[2];
    const float* w10  = (const float*)d_in[3];
    const float* b10  = (const float*)d_in[4];
    const float* w15  = (const float*)d_in[5];
    const float* b15  = (const float*)d_in[6];
    const float* gw   = (const float*)d_in[7];
    const float* gb   = (const float*)d_in[8];
    const float* mw   = (const float*)d_in[9];
    const float* mb   = (const float*)d_in[10];
    const float* gamma= (const float*)d_in[11];
    const float* beta = (const float*)d_in[12];
    float* out = (float*)d_out;

    const int smem1 = (32*PPAD + NFRAG1*128 + 24 + 8) * 4;
    const int smem2 = (24*PLANE + STEPS2*NT2*2*32*2 + K2 + 16 + 128 + 8) * 4;
    cudaFuncSetAttribute(k_conv1, cudaFuncAttributeMaxDynamicSharedMemorySize, smem1);
    cudaFuncSetAttribute(k_conv2, cudaFuncAttributeMaxDynamicSharedMemorySize, smem2);

    k_pool5   <<<(921600 + 255) / 256, 256>>>(x);
    k_poolrest<<<(332800 + 255) / 256, 256>>>();
    k_prepw   <<<32, 256>>>(w5, w10, w15, gw, mw);

    dim3 grid(GX, GY, 32);
    k_conv1<<<grid, 256, smem1>>>(x, b5, b10, b15);
    k_conv2<<<grid, 256, smem2>>>(gb, mb, out);

    k_stats<<<1, 256>>>(gamma, beta);
    k_norm <<<(5760000 + 255) / 256, 256>>>(out);
}